// round 2
// baseline (speedup 1.0000x reference)
#include <cuda_runtime.h>
#include <math.h>

#define BN 8
#define LSEQ 1024
#define DM 192
#define DI 384
#define DS 16
#define DR 12
#define IMG 512
#define ROWS (BN*LSEQ)   // 8192

// ---------------- scratch (__device__ globals: allocation-free) ----------------
__device__ float g_pwT[768*DM];            // transposed patch weights
__device__ float g_seq[ROWS*DM];           // patch embed out (b,l,m)
__device__ float g_xz[ROWS*2*DI];          // in_proj out: [:,:384]=u_raw, [:,384:]=z
__device__ float g_u[ROWS*DI];             // conv1d+silu out
__device__ float g_dbc[ROWS*44];           // x_proj out (dt|B|C)
__device__ float g_delta[ROWS*DI];         // softplus(dt@dtw+b)
__device__ float g_y[ROWS*DI];             // scan out, gated in place
__device__ float g_go[ROWS*DM];            // out_proj out (= g tensor)
__device__ float g_d[(size_t)BN*64*IMG*IMG]; // deconv+relu out (537MB)

// ---------------- helpers ----------------
__device__ __forceinline__ float silu_f(float x){ return x / (1.f + expf(-x)); }
__device__ __forceinline__ float softplus_f(float x){
    return x > 0.f ? x + log1pf(expf(-x)) : log1pf(expf(x));
}

// ---------------- K0: transpose patch weights ----------------
__global__ void k_transpose_pw(const float* __restrict__ pw){
    int idx = blockIdx.x*blockDim.x + threadIdx.x;
    if (idx >= 768*DM) return;
    int m = idx / 768, i = idx % 768;
    g_pwT[i*DM + m] = pw[m*768 + i];
}

// ---------------- K1: patch embed ----------------
// one block per (b,l); 192 threads (one per output channel)
__global__ void k_patch_embed(const float* __restrict__ x, const float* __restrict__ pb){
    int bl = blockIdx.x;
    int b = bl >> 10, l = bl & 1023;
    int ph = l >> 5, pw = l & 31;
    __shared__ float xs[768];
    for (int i = threadIdx.x; i < 768; i += blockDim.x){
        int c = i >> 8, p = (i >> 4) & 15, q = i & 15;
        xs[i] = x[(((size_t)b*3 + c)*IMG + ph*16 + p)*IMG + pw*16 + q];
    }
    __syncthreads();
    int m = threadIdx.x;
    float acc = pb[m];
    #pragma unroll 8
    for (int i = 0; i < 768; i++)
        acc = fmaf(xs[i], g_pwT[i*DM + m], acc);
    g_seq[(size_t)bl*DM + m] = acc;
}

// ---------------- K2: generic NT GEMM: C[M,N] = A[M,K] * B[N,K]^T ----------------
__global__ void k_gemm_nt(const float* __restrict__ A, const float* __restrict__ B,
                          float* __restrict__ C, int M, int N, int K){
    const int BM=64, BNt=64, BK=16;
    __shared__ float As[BK][BM];
    __shared__ float Bs[BK][BNt];
    int m0 = blockIdx.y*BM, n0 = blockIdx.x*BNt;
    int tid = threadIdx.x;
    int tx = tid & 15, ty = tid >> 4;
    float acc[4][4] = {};
    for (int k0 = 0; k0 < K; k0 += BK){
        for (int t = tid; t < BM*BK; t += 256){
            int r = t >> 4, c = t & 15;
            int mm = m0 + r, kk = k0 + c;
            As[c][r] = (mm < M && kk < K) ? A[(size_t)mm*K + kk] : 0.f;
        }
        for (int t = tid; t < BNt*BK; t += 256){
            int r = t >> 4, c = t & 15;
            int nn = n0 + r, kk = k0 + c;
            Bs[c][r] = (nn < N && kk < K) ? B[(size_t)nn*K + kk] : 0.f;
        }
        __syncthreads();
        #pragma unroll
        for (int kk = 0; kk < BK; kk++){
            float a[4], bb[4];
            #pragma unroll
            for (int i=0;i<4;i++) a[i]  = As[kk][ty*4+i];
            #pragma unroll
            for (int j=0;j<4;j++) bb[j] = Bs[kk][tx*4+j];
            #pragma unroll
            for (int i=0;i<4;i++)
                #pragma unroll
                for (int j=0;j<4;j++) acc[i][j] = fmaf(a[i], bb[j], acc[i][j]);
        }
        __syncthreads();
    }
    #pragma unroll
    for (int i=0;i<4;i++){
        int mm = m0 + ty*4 + i; if (mm >= M) continue;
        #pragma unroll
        for (int j=0;j<4;j++){
            int nn = n0 + tx*4 + j;
            if (nn < N) C[(size_t)mm*N + nn] = acc[i][j];
        }
    }
}

// ---------------- K3: depthwise causal conv1d + silu ----------------
__global__ void k_conv1d_silu(const float* __restrict__ cw, const float* __restrict__ cb){
    int idx = blockIdx.x*blockDim.x + threadIdx.x;
    if (idx >= ROWS*DI) return;
    int d = idx % DI;
    int row = idx / DI;          // b*1024 + l
    int l = row & 1023;
    float acc = cb[d];
    #pragma unroll
    for (int j = 0; j < 4; j++){
        int ll = l - 3 + j;
        if (ll >= 0)
            acc = fmaf(g_xz[(size_t)(row - l + ll)*(2*DI) + d], cw[d*4 + j], acc);
    }
    g_u[idx] = silu_f(acc);
}

// ---------------- K4: dt_proj + softplus -> delta ----------------
__global__ void k_delta(const float* __restrict__ dtw, const float* __restrict__ dtb){
    int idx = blockIdx.x*blockDim.x + threadIdx.x;
    if (idx >= ROWS*DI) return;
    int d = idx % DI;
    int row = idx / DI;
    float acc = dtb[d];
    const float* dbc = &g_dbc[(size_t)row*44];
    #pragma unroll
    for (int r = 0; r < DR; r++)
        acc = fmaf(dbc[r], dtw[d*DR + r], acc);
    g_delta[idx] = softplus_f(acc);
}

// ---------------- K5: selective scan ----------------
// 16 lanes per (b,d) channel, one lane per state n. 3072 groups.
__global__ void k_scan(const float* __restrict__ A_log, const float* __restrict__ Dv){
    int gid = blockIdx.x*(blockDim.x/16) + (threadIdx.x >> 4);
    int n = threadIdx.x & 15;
    if (gid >= BN*DI) return;
    int b = gid / DI, d = gid % DI;
    float a2 = -expf(A_log[d*DS + n]) * 1.4426950408889634f;  // A * log2(e)
    float Dd = Dv[d];
    float h = 0.f;
    size_t base = (size_t)b*LSEQ;
    for (int l = 0; l < LSEQ; l++){
        size_t row = base + l;
        float dv = g_delta[row*DI + d];
        float uv = g_u[row*DI + d];
        float Bv = g_dbc[row*44 + 12 + n];
        float Cv = g_dbc[row*44 + 28 + n];
        float dA = exp2f(dv * a2);
        h = fmaf(dA, h, dv * Bv * uv);
        float p = h * Cv;
        p += __shfl_xor_sync(0xffffffffu, p, 8);
        p += __shfl_xor_sync(0xffffffffu, p, 4);
        p += __shfl_xor_sync(0xffffffffu, p, 2);
        p += __shfl_xor_sync(0xffffffffu, p, 1);
        if (n == 0) g_y[row*DI + d] = p + uv * Dd;
    }
}

// ---------------- K6: gating y *= silu(z) ----------------
__global__ void k_gate(){
    int idx = blockIdx.x*blockDim.x + threadIdx.x;
    if (idx >= ROWS*DI) return;
    int row = idx / DI, d = idx % DI;
    float z = g_xz[(size_t)row*(2*DI) + DI + d];
    g_y[idx] *= silu_f(z);
}

// ---------------- K8: deconv as NN GEMM + relu + scatter ----------------
// C[m][n] = sum_c g_go[m][c] * Wd[c][n];  m=b*1024+l, n=dd*256+p*16+q
__global__ void k_deconv(const float* __restrict__ Wd, const float* __restrict__ bias){
    const int BM=64, BNt=64, BK=16;   // M=8192, N=16384, K=192
    __shared__ float As[BK][BM];
    __shared__ float Bs[BK][BNt];
    int m0 = blockIdx.y*BM, n0 = blockIdx.x*BNt;
    int tid = threadIdx.x;
    int tx = tid & 15, ty = tid >> 4;
    float acc[4][4] = {};
    for (int k0 = 0; k0 < DM; k0 += BK){
        // A tile: 64 rows x 16 k, one float4 per thread along k (g_go K=192, 16|192)
        {
            int r = tid >> 2, c4 = (tid & 3) * 4;   // row 0..63, k-offset 0,4,8,12
            const float4 v = *(const float4*)&g_go[(size_t)(m0 + r)*DM + k0 + c4];
            As[c4+0][r] = v.x; As[c4+1][r] = v.y; As[c4+2][r] = v.z; As[c4+3][r] = v.w;
        }
        // B tile: 16 k-rows x 64 n, one float4 per thread along n (Wd rows 16384, 64-aligned)
        {
            int c = tid >> 4, r4 = (tid & 15) * 4;  // k-row 0..15, n-offset 0..60
            const float4 v = *(const float4*)&Wd[(size_t)(k0 + c)*16384 + n0 + r4];
            Bs[c][r4+0] = v.x; Bs[c][r4+1] = v.y; Bs[c][r4+2] = v.z; Bs[c][r4+3] = v.w;
        }
        __syncthreads();
        #pragma unroll
        for (int kk = 0; kk < BK; kk++){
            float a[4], bb[4];
            #pragma unroll
            for (int i=0;i<4;i++) a[i]  = As[kk][ty*4+i];
            #pragma unroll
            for (int j=0;j<4;j++) bb[j] = Bs[kk][tx*4+j];
            #pragma unroll
            for (int i=0;i<4;i++)
                #pragma unroll
                for (int j=0;j<4;j++) acc[i][j] = fmaf(a[i], bb[j], acc[i][j]);
        }
        __syncthreads();
    }
    int dd = (n0 >> 8);                 // constant per block (n0 aligned 64)
    float bv = bias[dd];
    #pragma unroll
    for (int i=0;i<4;i++){
        int m = m0 + ty*4 + i;
        int b = m >> 10, l = m & 1023;
        int hh = l >> 5, ww = l & 31;
        #pragma unroll
        for (int j=0;j<4;j++){
            int n = n0 + tx*4 + j;
            int pq = n & 255, p = pq >> 4, q = pq & 15;
            float v = fmaxf(acc[i][j] + bv, 0.f);
            g_d[(((size_t)b*64 + dd)*IMG + hh*16 + p)*IMG + ww*16 + q] = v;
        }
    }
}

// ---------------- K9: 3x3 conv (pad 1) + sigmoid ----------------
__global__ void k_conv3_sig(const float* __restrict__ W3, const float* __restrict__ b3,
                            float* __restrict__ out){
    int b = blockIdx.z;
    int ty0 = blockIdx.y*16, tx0 = blockIdx.x*16;
    __shared__ float ws[3*64*9];
    __shared__ float ds[16][18][18];
    int tid = threadIdx.x;
    for (int i = tid; i < 1728; i += 256) ws[i] = W3[i];
    int yy = tid >> 4, xx = tid & 15;
    float acc0 = b3[0], acc1 = b3[1], acc2 = b3[2];
    for (int dd0 = 0; dd0 < 64; dd0 += 16){
        __syncthreads();
        for (int i = tid; i < 16*18*18; i += 256){
            int dl = i / 324, r = i % 324;
            int ry = r / 18, rx = r % 18;
            int Hy = ty0 + ry - 1, Wx = tx0 + rx - 1;
            float v = 0.f;
            if (Hy >= 0 && Hy < IMG && Wx >= 0 && Wx < IMG)
                v = g_d[(((size_t)b*64 + dd0 + dl)*IMG + Hy)*IMG + Wx];
            ds[dl][ry][rx] = v;
        }
        __syncthreads();
        #pragma unroll
        for (int dl = 0; dl < 16; dl++){
            int wbase = (dd0 + dl)*9;
            #pragma unroll
            for (int i = 0; i < 3; i++){
                #pragma unroll
                for (int j = 0; j < 3; j++){
                    float v = ds[dl][yy+i][xx+j];
                    int wi = wbase + i*3 + j;
                    acc0 = fmaf(v, ws[wi],        acc0);
                    acc1 = fmaf(v, ws[576 + wi],  acc1);
                    acc2 = fmaf(v, ws[1152 + wi], acc2);
                }
            }
        }
    }
    int Hp = ty0 + yy, Wp = tx0 + xx;
    out[(((size_t)b*3 + 0)*IMG + Hp)*IMG + Wp] = 1.f/(1.f + expf(-acc0));
    out[(((size_t)b*3 + 1)*IMG + Hp)*IMG + Wp] = 1.f/(1.f + expf(-acc1));
    out[(((size_t)b*3 + 2)*IMG + Hp)*IMG + Wp] = 1.f/(1.f + expf(-acc2));
}

// ---------------- launch ----------------
extern "C" void kernel_launch(void* const* d_in, const int* in_sizes, int n_in,
                              void* d_out, int out_size){
    const float* x        = (const float*)d_in[0];
    const float* patch_w  = (const float*)d_in[1];
    const float* patch_b  = (const float*)d_in[2];
    const float* in_proj_w= (const float*)d_in[3];
    const float* conv1d_w = (const float*)d_in[4];
    const float* conv1d_b = (const float*)d_in[5];
    const float* x_proj_w = (const float*)d_in[6];
    const float* dt_proj_w= (const float*)d_in[7];
    const float* dt_proj_b= (const float*)d_in[8];
    const float* A_log    = (const float*)d_in[9];
    const float* Dv       = (const float*)d_in[10];
    const float* out_proj_w=(const float*)d_in[11];
    const float* deconv_w = (const float*)d_in[12];
    const float* deconv_b = (const float*)d_in[13];
    const float* dec_conv_w=(const float*)d_in[14];
    const float* dec_conv_b=(const float*)d_in[15];
    float* out = (float*)d_out;

    float *p_seq, *p_xz, *p_u, *p_dbc, *p_y, *p_go;
    cudaGetSymbolAddress((void**)&p_seq, g_seq);
    cudaGetSymbolAddress((void**)&p_xz,  g_xz);
    cudaGetSymbolAddress((void**)&p_u,   g_u);
    cudaGetSymbolAddress((void**)&p_dbc, g_dbc);
    cudaGetSymbolAddress((void**)&p_y,   g_y);
    cudaGetSymbolAddress((void**)&p_go,  g_go);

    // K0: transpose patch weights
    k_transpose_pw<<<(768*DM + 255)/256, 256>>>(patch_w);
    // K1: patch embed
    k_patch_embed<<<ROWS, DM>>>(x, patch_b);
    // K2: in_proj  (8192 x 768, K=192)
    {
        dim3 grid(768/64, ROWS/64);
        k_gemm_nt<<<grid, 256>>>(p_seq, in_proj_w, p_xz, ROWS, 2*DI, DM);
    }
    // K3: conv1d + silu
    k_conv1d_silu<<<(ROWS*DI + 255)/256, 256>>>(conv1d_w, conv1d_b);
    // x_proj (8192 x 44, K=384)
    {
        dim3 grid(1, ROWS/64);
        k_gemm_nt<<<grid, 256>>>(p_u, x_proj_w, p_dbc, ROWS, 44, DI);
    }
    // K4: delta
    k_delta<<<(ROWS*DI + 255)/256, 256>>>(dt_proj_w, dt_proj_b);
    // K5: scan  (3072 groups of 16 lanes)
    k_scan<<<(BN*DI*16)/256, 256>>>(A_log, Dv);
    // K6: gate
    k_gate<<<(ROWS*DI + 255)/256, 256>>>();
    // out_proj (8192 x 192, K=384)
    {
        dim3 grid(192/64, ROWS/64);
        k_gemm_nt<<<grid, 256>>>(p_y, out_proj_w, p_go, ROWS, DM, DI);
    }
    // K8: deconv GEMM (8192 x 16384, K=192) + relu + scatter
    {
        dim3 grid(16384/64, ROWS/64);
        k_deconv<<<grid, 256>>>(deconv_w, deconv_b);
    }
    // K9: 3x3 conv + sigmoid
    {
        dim3 grid(IMG/16, IMG/16, BN);
        k_conv3_sig<<<grid, 256>>>(dec_conv_w, dec_conv_b, out);
    }
}

// round 5
// speedup vs baseline: 1.5948x; 1.5948x over previous
#include <cuda_runtime.h>
#include <cuda_bf16.h>
#include <cstdint>
#include <math.h>

#define BN 8
#define LSEQ 1024
#define DM 192
#define DI 384
#define DS 16
#define DR 12
#define IMG 512
#define ROWS (BN*LSEQ)   // 8192

typedef unsigned int u32;

// ---------------- scratch (__device__ globals: allocation-free) ----------------
__device__ float g_pwT[768*DM];            // transposed patch weights
__device__ float g_seq[ROWS*DM];           // patch embed out (b,l,m)
__device__ float g_xz[ROWS*2*DI];          // in_proj out: [:,:384]=u_raw, [:,384:]=z
__device__ float g_u[ROWS*DI];             // conv1d+silu out
__device__ float g_dbc[ROWS*44];           // x_proj out (dt|B|C)
__device__ float g_delta[ROWS*DI];         // softplus(dt@dtw+b)
__device__ float g_y[ROWS*DI];             // scan out, gated in place
__device__ float g_go[ROWS*DM];            // out_proj out (= g tensor)
__device__ __nv_bfloat16 g_gobf[ROWS*DM];  // bf16 copy of g_go
__device__ __nv_bfloat16 g_wdT[16384*DM];  // deconv weights transposed [n][k] bf16
__device__ float g_d[(size_t)BN*64*IMG*IMG]; // deconv+relu out (537MB)

// ---------------- helpers ----------------
__device__ __forceinline__ float silu_f(float x){ return x / (1.f + expf(-x)); }
__device__ __forceinline__ float softplus_f(float x){
    return x > 0.f ? x + log1pf(expf(-x)) : log1pf(expf(x));
}
__device__ __forceinline__ void ldsm4(u32 &r0, u32 &r1, u32 &r2, u32 &r3, const void* p){
    u32 a = (u32)__cvta_generic_to_shared((void*)p);
    asm volatile("ldmatrix.sync.aligned.m8n8.x4.shared.b16 {%0,%1,%2,%3}, [%4];"
                 : "=r"(r0), "=r"(r1), "=r"(r2), "=r"(r3) : "r"(a));
}
__device__ __forceinline__ void mma16816(float* c, u32 a0, u32 a1, u32 a2, u32 a3,
                                         u32 b0, u32 b1){
    asm volatile("mma.sync.aligned.m16n8k16.row.col.f32.bf16.bf16.f32 "
                 "{%0,%1,%2,%3}, {%4,%5,%6,%7}, {%8,%9}, {%0,%1,%2,%3};"
                 : "+f"(c[0]), "+f"(c[1]), "+f"(c[2]), "+f"(c[3])
                 : "r"(a0), "r"(a1), "r"(a2), "r"(a3), "r"(b0), "r"(b1));
}

// ---------------- K0: transpose patch weights ----------------
__global__ void k_transpose_pw(const float* __restrict__ pw){
    int idx = blockIdx.x*blockDim.x + threadIdx.x;
    if (idx >= 768*DM) return;
    int m = idx / 768;
    int i = idx % 768;
    g_pwT[i*DM + m] = pw[m*768 + i];
}

// ---------------- K1: patch embed ----------------
__global__ void k_patch_embed(const float* __restrict__ x, const float* __restrict__ pb){
    int bl = blockIdx.x;
    int b = bl >> 10;
    int l = bl & 1023;
    int ph = l >> 5;
    int pw = l & 31;
    __shared__ float xs[768];
    for (int i = threadIdx.x; i < 768; i += blockDim.x){
        int c = i >> 8;
        int p = (i >> 4) & 15;
        int q = i & 15;
        xs[i] = x[(((size_t)b*3 + c)*IMG + ph*16 + p)*IMG + pw*16 + q];
    }
    __syncthreads();
    int m = threadIdx.x;
    float acc = pb[m];
    #pragma unroll 8
    for (int i = 0; i < 768; i++)
        acc = fmaf(xs[i], g_pwT[i*DM + m], acc);
    g_seq[(size_t)bl*DM + m] = acc;
}

// ---------------- K2: generic NT GEMM: C[M,N] = A[M,K] * B[N,K]^T ----------------
__global__ void k_gemm_nt(const float* __restrict__ A, const float* __restrict__ B,
                          float* __restrict__ C, int M, int N, int K){
    const int BM = 64, BNt = 64, BK = 16;
    __shared__ float As[BK][BM];
    __shared__ float Bs[BK][BNt];
    int m0 = blockIdx.y*BM;
    int n0 = blockIdx.x*BNt;
    int tid = threadIdx.x;
    int tx = tid & 15;
    int ty = tid >> 4;
    float acc[4][4] = {};
    for (int k0 = 0; k0 < K; k0 += BK){
        for (int t = tid; t < BM*BK; t += 256){
            int r = t >> 4;
            int c = t & 15;
            int mm = m0 + r;
            int kk = k0 + c;
            As[c][r] = (mm < M && kk < K) ? A[(size_t)mm*K + kk] : 0.f;
        }
        for (int t = tid; t < BNt*BK; t += 256){
            int r = t >> 4;
            int c = t & 15;
            int nn = n0 + r;
            int kk = k0 + c;
            Bs[c][r] = (nn < N && kk < K) ? B[(size_t)nn*K + kk] : 0.f;
        }
        __syncthreads();
        #pragma unroll
        for (int kk = 0; kk < BK; kk++){
            float a[4], bb[4];
            #pragma unroll
            for (int i = 0; i < 4; i++) a[i]  = As[kk][ty*4+i];
            #pragma unroll
            for (int j = 0; j < 4; j++) bb[j] = Bs[kk][tx*4+j];
            #pragma unroll
            for (int i = 0; i < 4; i++){
                #pragma unroll
                for (int j = 0; j < 4; j++) acc[i][j] = fmaf(a[i], bb[j], acc[i][j]);
            }
        }
        __syncthreads();
    }
    #pragma unroll
    for (int i = 0; i < 4; i++){
        int mm = m0 + ty*4 + i;
        if (mm >= M) continue;
        #pragma unroll
        for (int j = 0; j < 4; j++){
            int nn = n0 + tx*4 + j;
            if (nn < N) C[(size_t)mm*N + nn] = acc[i][j];
        }
    }
}

// ---------------- K3: depthwise causal conv1d + silu ----------------
__global__ void k_conv1d_silu(const float* __restrict__ cw, const float* __restrict__ cb){
    int idx = blockIdx.x*blockDim.x + threadIdx.x;
    if (idx >= ROWS*DI) return;
    int d = idx % DI;
    int row = idx / DI;          // b*1024 + l
    int l = row & 1023;
    float acc = cb[d];
    #pragma unroll
    for (int j = 0; j < 4; j++){
        int ll = l - 3 + j;
        if (ll >= 0)
            acc = fmaf(g_xz[(size_t)(row - l + ll)*(2*DI) + d], cw[d*4 + j], acc);
    }
    g_u[idx] = silu_f(acc);
}

// ---------------- K4: dt_proj + softplus -> delta ----------------
__global__ void k_delta(const float* __restrict__ dtw, const float* __restrict__ dtb){
    int idx = blockIdx.x*blockDim.x + threadIdx.x;
    if (idx >= ROWS*DI) return;
    int d = idx % DI;
    int row = idx / DI;
    float acc = dtb[d];
    const float* dbc = &g_dbc[(size_t)row*44];
    #pragma unroll
    for (int r = 0; r < DR; r++)
        acc = fmaf(dbc[r], dtw[d*DR + r], acc);
    g_delta[idx] = softplus_f(acc);
}

// ---------------- K5: selective scan ----------------
__global__ void k_scan(const float* __restrict__ A_log, const float* __restrict__ Dv){
    int gid = blockIdx.x*(blockDim.x/16) + (threadIdx.x >> 4);
    int n = threadIdx.x & 15;
    if (gid >= BN*DI) return;
    int b = gid / DI;
    int d = gid % DI;
    float a2 = -expf(A_log[d*DS + n]) * 1.4426950408889634f;  // A * log2(e)
    float Dd = Dv[d];
    float h = 0.f;
    size_t base = (size_t)b*LSEQ;
    for (int l = 0; l < LSEQ; l++){
        size_t row = base + l;
        float dv = g_delta[row*DI + d];
        float uv = g_u[row*DI + d];
        float Bv = g_dbc[row*44 + 12 + n];
        float Cv = g_dbc[row*44 + 28 + n];
        float dA = exp2f(dv * a2);
        h = fmaf(dA, h, dv * Bv * uv);
        float p = h * Cv;
        p += __shfl_xor_sync(0xffffffffu, p, 8);
        p += __shfl_xor_sync(0xffffffffu, p, 4);
        p += __shfl_xor_sync(0xffffffffu, p, 2);
        p += __shfl_xor_sync(0xffffffffu, p, 1);
        if (n == 0) g_y[row*DI + d] = p + uv * Dd;
    }
}

// ---------------- K6: gating y *= silu(z) ----------------
__global__ void k_gate(){
    int idx = blockIdx.x*blockDim.x + threadIdx.x;
    if (idx >= ROWS*DI) return;
    int row = idx / DI;
    int d = idx % DI;
    float z = g_xz[(size_t)row*(2*DI) + DI + d];
    g_y[idx] *= silu_f(z);
}

// ---------------- K7a: g_go fp32 -> bf16 ----------------
__global__ void k_f2bf(){
    int idx = blockIdx.x*blockDim.x + threadIdx.x;
    if (idx >= ROWS*DM) return;
    g_gobf[idx] = __float2bfloat16(g_go[idx]);
}

// ---------------- K7b: Wd [192][16384] fp32 -> WdT [16384][192] bf16 ----------------
__global__ void k_prep_wdT(const float* __restrict__ Wd){
    __shared__ float t[32][33];
    int n0 = blockIdx.x*32;
    int k0 = blockIdx.y*32;
    int tx = threadIdx.x & 31;
    int ty = threadIdx.x >> 5;   // 256 threads: ty 0..7
    for (int i = ty; i < 32; i += 8)
        t[i][tx] = Wd[(size_t)(k0+i)*16384 + n0 + tx];
    __syncthreads();
    for (int i = ty; i < 32; i += 8)
        g_wdT[(size_t)(n0+i)*DM + k0 + tx] = __float2bfloat16(t[tx][i]);
}

// ---------------- K8: deconv GEMM via bf16 tensor-core MMA ----------------
// C[m][n] = sum_k g_gobf[m][k] * g_wdT[n][k]; relu(+bias) -> scatter to g_d
// CTA: 128x128 tile, full K=192 resident. 8 warps = 2(m) x 4(n).
#define LDA 200   // padded row stride (bf16): 400B == 4 words mod 32 -> conflict-free LDSM
#define SMEM_DECONV (2*128*LDA*2)
__global__ void __launch_bounds__(256, 2) k_deconv_mma(const float* __restrict__ bias){
    extern __shared__ __align__(16) char smem_raw[];
    __nv_bfloat16* As = (__nv_bfloat16*)smem_raw;     // [128][LDA]
    __nv_bfloat16* Bs = As + 128*LDA;                  // [128][LDA]
    int n0 = blockIdx.x*128;
    int m0 = blockIdx.y*128;
    int tid = threadIdx.x;

    // load A tile: 128 rows x 192 bf16 (two 96-elem halves per row, 12 uint4 each)
    {
        int row = tid >> 1;
        int hv = tid & 1;
        const uint4* src = (const uint4*)&g_gobf[(size_t)(m0+row)*DM + hv*96];
        uint4* dst = (uint4*)(As + row*LDA + hv*96);
        #pragma unroll
        for (int i = 0; i < 12; i++) dst[i] = src[i];
    }
    // load B tile: 128 rows (n) x 192 bf16
    {
        int row = tid >> 1;
        int hv = tid & 1;
        const uint4* src = (const uint4*)&g_wdT[(size_t)(n0+row)*DM + hv*96];
        uint4* dst = (uint4*)(Bs + row*LDA + hv*96);
        #pragma unroll
        for (int i = 0; i < 12; i++) dst[i] = src[i];
    }
    __syncthreads();

    int w = tid >> 5;
    int lane = tid & 31;
    int wm = (w & 1)*64;
    int wn = (w >> 1)*32;
    int lrow = lane & 15;            // ldmatrix row-within-16
    int lcol = (lane >> 4)*8;        // ldmatrix k-offset 0/8
    float acc[4][4][4];
    #pragma unroll
    for (int i = 0; i < 4; i++){
        #pragma unroll
        for (int j = 0; j < 4; j++){
            #pragma unroll
            for (int r = 0; r < 4; r++) acc[i][j][r] = 0.f;
        }
    }

    #pragma unroll
    for (int ks = 0; ks < 12; ks++){
        int k = ks*16;
        u32 ar[4][4];
        #pragma unroll
        for (int mf = 0; mf < 4; mf++)
            ldsm4(ar[mf][0], ar[mf][1], ar[mf][2], ar[mf][3],
                  As + (wm + mf*16 + lrow)*LDA + k + lcol);
        u32 br[2][4];
        #pragma unroll
        for (int np = 0; np < 2; np++)
            ldsm4(br[np][0], br[np][1], br[np][2], br[np][3],
                  Bs + (wn + np*16 + lrow)*LDA + k + lcol);
        #pragma unroll
        for (int mf = 0; mf < 4; mf++){
            #pragma unroll
            for (int nf = 0; nf < 4; nf++){
                mma16816(acc[mf][nf], ar[mf][0], ar[mf][1], ar[mf][2], ar[mf][3],
                         br[nf>>1][nf&1], br[nf>>1][2 + (nf&1)]);
            }
        }
    }

    // epilogue: bias + relu + patch scatter
    int dd = n0 >> 8;                  // constant per CTA (128-tile never crosses 256)
    float bv = bias[dd];
    int grp = lane >> 2;
    int tq = lane & 3;
    #pragma unroll
    for (int mf = 0; mf < 4; mf++){
        #pragma unroll
        for (int nf = 0; nf < 4; nf++){
            int n = n0 + wn + nf*8 + 2*tq;
            int p = (n >> 4) & 15;
            int q = n & 15;
            #pragma unroll
            for (int hv = 0; hv < 2; hv++){
                int m = m0 + wm + mf*16 + grp + hv*8;
                int b = m >> 10;
                int l = m & 1023;
                int hh = l >> 5;
                int ww = l & 31;
                float2 v;
                v.x = fmaxf(acc[mf][nf][hv*2+0] + bv, 0.f);
                v.y = fmaxf(acc[mf][nf][hv*2+1] + bv, 0.f);
                *(float2*)&g_d[(((size_t)b*64 + dd)*IMG + hh*16 + p)*IMG + ww*16 + q] = v;
            }
        }
    }
}

// ---------------- K9: 3x3 conv (pad 1) + sigmoid ----------------
__global__ void k_conv3_sig(const float* __restrict__ W3, const float* __restrict__ b3,
                            float* __restrict__ out){
    int b = blockIdx.z;
    int ty0 = blockIdx.y*16;
    int tx0 = blockIdx.x*16;
    __shared__ float ws[3*64*9];
    __shared__ float ds[16][18][18];
    int tid = threadIdx.x;
    for (int i = tid; i < 1728; i += 256) ws[i] = W3[i];
    int yy = tid >> 4;
    int xx = tid & 15;
    float acc0 = b3[0];
    float acc1 = b3[1];
    float acc2 = b3[2];
    for (int dd0 = 0; dd0 < 64; dd0 += 16){
        __syncthreads();
        for (int i = tid; i < 16*18*18; i += 256){
            int dl = i / 324;
            int r = i % 324;
            int ry = r / 18;
            int rx = r % 18;
            int Hy = ty0 + ry - 1;
            int Wx = tx0 + rx - 1;
            float v = 0.f;
            if (Hy >= 0 && Hy < IMG && Wx >= 0 && Wx < IMG)
                v = g_d[(((size_t)b*64 + dd0 + dl)*IMG + Hy)*IMG + Wx];
            ds[dl][ry][rx] = v;
        }
        __syncthreads();
        #pragma unroll
        for (int dl = 0; dl < 16; dl++){
            int wbase = (dd0 + dl)*9;
            #pragma unroll
            for (int i = 0; i < 3; i++){
                #pragma unroll
                for (int j = 0; j < 3; j++){
                    float v = ds[dl][yy+i][xx+j];
                    int wi = wbase + i*3 + j;
                    acc0 = fmaf(v, ws[wi],        acc0);
                    acc1 = fmaf(v, ws[576 + wi],  acc1);
                    acc2 = fmaf(v, ws[1152 + wi], acc2);
                }
            }
        }
    }
    int Hp = ty0 + yy;
    int Wp = tx0 + xx;
    out[(((size_t)b*3 + 0)*IMG + Hp)*IMG + Wp] = 1.f/(1.f + expf(-acc0));
    out[(((size_t)b*3 + 1)*IMG + Hp)*IMG + Wp] = 1.f/(1.f + expf(-acc1));
    out[(((size_t)b*3 + 2)*IMG + Hp)*IMG + Wp] = 1.f/(1.f + expf(-acc2));
}

// ---------------- launch ----------------
extern "C" void kernel_launch(void* const* d_in, const int* in_sizes, int n_in,
                              void* d_out, int out_size){
    const float* x         = (const float*)d_in[0];
    const float* patch_w   = (const float*)d_in[1];
    const float* patch_b   = (const float*)d_in[2];
    const float* in_proj_w = (const float*)d_in[3];
    const float* conv1d_w  = (const float*)d_in[4];
    const float* conv1d_b  = (const float*)d_in[5];
    const float* x_proj_w  = (const float*)d_in[6];
    const float* dt_proj_w = (const float*)d_in[7];
    const float* dt_proj_b = (const float*)d_in[8];
    const float* A_log     = (const float*)d_in[9];
    const float* Dv        = (const float*)d_in[10];
    const float* out_proj_w= (const float*)d_in[11];
    const float* deconv_w  = (const float*)d_in[12];
    const float* deconv_b  = (const float*)d_in[13];
    const float* dec_conv_w= (const float*)d_in[14];
    const float* dec_conv_b= (const float*)d_in[15];
    float* out = (float*)d_out;

    float *p_seq, *p_xz, *p_u, *p_dbc, *p_y, *p_go;
    cudaGetSymbolAddress((void**)&p_seq, g_seq);
    cudaGetSymbolAddress((void**)&p_xz,  g_xz);
    cudaGetSymbolAddress((void**)&p_u,   g_u);
    cudaGetSymbolAddress((void**)&p_dbc, g_dbc);
    cudaGetSymbolAddress((void**)&p_y,   g_y);
    cudaGetSymbolAddress((void**)&p_go,  g_go);

    cudaFuncSetAttribute(k_deconv_mma, cudaFuncAttributeMaxDynamicSharedMemorySize, SMEM_DECONV);

    // K0: transpose patch weights ; prep deconv weights (independent)
    k_transpose_pw<<<(768*DM + 255)/256, 256>>>(patch_w);
    {
        dim3 grid(16384/32, DM/32);
        k_prep_wdT<<<grid, 256>>>(deconv_w);
    }
    // K1: patch embed
    k_patch_embed<<<ROWS, DM>>>(x, patch_b);
    // K2: in_proj  (8192 x 768, K=192)
    {
        dim3 grid(768/64, ROWS/64);
        k_gemm_nt<<<grid, 256>>>(p_seq, in_proj_w, p_xz, ROWS, 2*DI, DM);
    }
    // K3: conv1d + silu
    k_conv1d_silu<<<(ROWS*DI + 255)/256, 256>>>(conv1d_w, conv1d_b);
    // x_proj (8192 x 44, K=384)
    {
        dim3 grid(1, ROWS/64);
        k_gemm_nt<<<grid, 256>>>(p_u, x_proj_w, p_dbc, ROWS, 44, DI);
    }
    // K4: delta
    k_delta<<<(ROWS*DI + 255)/256, 256>>>(dt_proj_w, dt_proj_b);
    // K5: scan
    k_scan<<<(BN*DI*16)/256, 256>>>(A_log, Dv);
    // K6: gate
    k_gate<<<(ROWS*DI + 255)/256, 256>>>();
    // out_proj (8192 x 192, K=384)
    {
        dim3 grid(192/64, ROWS/64);
        k_gemm_nt<<<grid, 256>>>(p_y, out_proj_w, p_go, ROWS, DM, DI);
    }
    // convert activations to bf16
    k_f2bf<<<(ROWS*DM + 255)/256, 256>>>();
    // K8: deconv via tensor cores (8192 x 16384, K=192) + relu + scatter
    {
        dim3 grid(16384/128, ROWS/128);
        k_deconv_mma<<<grid, 256, SMEM_DECONV>>>(deconv_b);
    }
    // K9: 3x3 conv + sigmoid
    {
        dim3 grid(IMG/16, IMG/16, BN);
        k_conv3_sig<<<grid, 256>>>(dec_conv_w, dec_conv_b, out);
    }
}